// round 1
// baseline (speedup 1.0000x reference)
#include <cuda_runtime.h>

// Problem constants
#define NPTS 16384
#define KNN  16
#define HDIM 64
#define CDIM 10
#define NPART 4                 // kNN partitions
#define PARTSZ (NPTS / NPART)   // 4096
#define TILE 1024
#define KBLK 128

#define FINF  __int_as_float(0x7f800000)
#define FNINF __int_as_float(0xff800000)

// ---- scratch (__device__ globals; no allocation allowed) ----
__device__ float4 g_pts[NPTS];                 // x,y,z,|p|^2
__device__ float  g_pd[NPART * NPTS * KNN];    // partial knn dists
__device__ int    g_pi[NPART * NPTS * KNN];    // partial knn idx
__device__ int    g_idx[NPTS * KNN];           // final knn idx
__device__ float  g_A1[NPTS * HDIM];           // x@(W1a-W1b)+b1
__device__ float  g_B1[NPTS * HDIM];           // x@W1b
__device__ float  g_h1[NPTS * HDIM];           // layer-1 output
__device__ float  g_A2[NPTS * HDIM];
__device__ float  g_B2[NPTS * HDIM];
__device__ int    g_gmax[HDIM];                // global max (float-as-int, relu>=0)

// ---------------------------------------------------------------------------
// K0: pack points, zero global max accumulator
__global__ void k_prep(const float* __restrict__ pos) {
    int i = blockIdx.x * blockDim.x + threadIdx.x;
    if (i < NPTS) {
        float x = pos[i * 3 + 0];
        float y = pos[i * 3 + 1];
        float z = pos[i * 3 + 2];
        g_pts[i] = make_float4(x, y, z, fmaf(z, z, fmaf(y, y, x * x)));
    }
    if (i < HDIM) g_gmax[i] = 0;
}

// ---------------------------------------------------------------------------
// K1: brute-force kNN over one partition of candidates per block-row.
// Each thread owns one query; candidate tiles staged in shared and read as
// warp-uniform broadcasts. Ranking key: d' = sq_j - 2*dot (sq_i constant).
__global__ __launch_bounds__(KBLK) void k_knn() {
    __shared__ float4 sh[TILE];
    int q = blockIdx.x * KBLK + threadIdx.x;
    float4 p = g_pts[q];
    float ax = -2.0f * p.x, ay = -2.0f * p.y, az = -2.0f * p.z;

    float dist[KNN];
    int   idxr[KNN];
#pragma unroll
    for (int s = 0; s < KNN; ++s) { dist[s] = FINF; idxr[s] = 0; }

    int base = blockIdx.y * PARTSZ;
    for (int t0 = 0; t0 < PARTSZ; t0 += TILE) {
        __syncthreads();
        for (int r = threadIdx.x; r < TILE; r += KBLK)
            sh[r] = g_pts[base + t0 + r];
        __syncthreads();
#pragma unroll 4
        for (int t = 0; t < TILE; ++t) {
            float4 cd = sh[t];
            float d = fmaf(ax, cd.x, fmaf(ay, cd.y, fmaf(az, cd.z, cd.w)));
            if (d < dist[KNN - 1]) {
                int j = base + t0 + t;
#pragma unroll
                for (int s = 0; s < KNN; ++s) {
                    bool c = d < dist[s];
                    float td = dist[s]; int ti = idxr[s];
                    dist[s] = c ? d : td;
                    idxr[s] = c ? j : ti;
                    d = c ? td : d;
                    j = c ? ti : j;
                }
            }
        }
    }
    int off = (blockIdx.y * NPTS + q) * KNN;
#pragma unroll
    for (int s = 0; s < KNN; ++s) { g_pd[off + s] = dist[s]; g_pi[off + s] = idxr[s]; }
}

// ---------------------------------------------------------------------------
// K2: merge NPART partial top-16 lists per query
__global__ void k_merge() {
    int i = blockIdx.x * blockDim.x + threadIdx.x;
    if (i >= NPTS) return;
    float dist[KNN];
    int   idxr[KNN];
#pragma unroll
    for (int s = 0; s < KNN; ++s) { dist[s] = FINF; idxr[s] = 0; }
    for (int pp = 0; pp < NPART; ++pp) {
        int off = (pp * NPTS + i) * KNN;
        for (int e = 0; e < KNN; ++e) {
            float d = g_pd[off + e];
            int   j = g_pi[off + e];
            if (d < dist[KNN - 1]) {
#pragma unroll
                for (int s = 0; s < KNN; ++s) {
                    bool c = d < dist[s];
                    float td = dist[s]; int ti = idxr[s];
                    dist[s] = c ? d : td;
                    idxr[s] = c ? j : ti;
                    d = c ? td : d;
                    j = c ? ti : j;
                }
            }
        }
    }
#pragma unroll
    for (int s = 0; s < KNN; ++s) g_idx[i * KNN + s] = idxr[s];
}

// ---------------------------------------------------------------------------
// K3: layer-1 projections. A1 = pos@(W1a-W1b)+b1, B1 = pos@W1b
__global__ void k_feat1(const float* __restrict__ W1, const float* __restrict__ b1) {
    int i = blockIdx.x * blockDim.x + threadIdx.x;
    if (i >= NPTS) return;
    float4 p = g_pts[i];
#pragma unroll 8
    for (int h = 0; h < HDIM; ++h) {
        float wa0 = W1[0 * HDIM + h], wa1 = W1[1 * HDIM + h], wa2 = W1[2 * HDIM + h];
        float wb0 = W1[3 * HDIM + h], wb1 = W1[4 * HDIM + h], wb2 = W1[5 * HDIM + h];
        float v = fmaf(p.x, wb0, fmaf(p.y, wb1, p.z * wb2));
        float u = fmaf(p.x, wa0 - wb0, fmaf(p.y, wa1 - wb1, p.z * (wa2 - wb2)));
        g_A1[i * HDIM + h] = u + b1[h];
        g_B1[i * HDIM + h] = v;
    }
}

// ---------------------------------------------------------------------------
// K4: h1 = relu(A1 + max_k B1[idx]) ; thread handles one (query, float4-quad)
__global__ __launch_bounds__(256) void k_gmax1() {
    int gt = blockIdx.x * 256 + threadIdx.x;
    int i = gt >> 4, q = gt & 15;
    const int* row = g_idx + i * KNN;
    float4 m = make_float4(FNINF, FNINF, FNINF, FNINF);
#pragma unroll
    for (int k = 0; k < KNN; ++k) {
        int j = __ldg(row + k);
        float4 v = reinterpret_cast<const float4*>(g_B1)[j * 16 + q];
        m.x = fmaxf(m.x, v.x); m.y = fmaxf(m.y, v.y);
        m.z = fmaxf(m.z, v.z); m.w = fmaxf(m.w, v.w);
    }
    float4 a = reinterpret_cast<const float4*>(g_A1)[i * 16 + q];
    float4 o;
    o.x = fmaxf(a.x + m.x, 0.0f); o.y = fmaxf(a.y + m.y, 0.0f);
    o.z = fmaxf(a.z + m.z, 0.0f); o.w = fmaxf(a.w + m.w, 0.0f);
    reinterpret_cast<float4*>(g_h1)[i * 16 + q] = o;
}

// ---------------------------------------------------------------------------
// K5: layer-2 projections. A2 = h1@(W2a-W2b)+b2, B2 = h1@W2b
// block: 16 rows x 16 quads; weights staged (combined) in shared.
__global__ __launch_bounds__(256) void k_feat2(const float* __restrict__ W2,
                                               const float* __restrict__ b2) {
    __shared__ float sWu[HDIM * HDIM];  // 16 KB
    __shared__ float sWv[HDIM * HDIM];  // 16 KB
    __shared__ float sX[16 * HDIM];     // 4 KB
    int tid = threadIdx.x;
    for (int e = tid; e < HDIM * HDIM; e += 256) {
        int j = e >> 6, h = e & 63;
        float wb = W2[(j + HDIM) * HDIM + h];
        sWv[e] = wb;
        sWu[e] = W2[j * HDIM + h] - wb;
    }
    int ty = tid >> 4, q = tid & 15;
    int i = blockIdx.x * 16 + ty;
    reinterpret_cast<float4*>(sX)[ty * 16 + q] =
        reinterpret_cast<const float4*>(g_h1)[i * 16 + q];
    __syncthreads();

    float4 au = make_float4(0.f, 0.f, 0.f, 0.f);
    float4 av = make_float4(0.f, 0.f, 0.f, 0.f);
#pragma unroll 8
    for (int j = 0; j < HDIM; ++j) {
        float xj = sX[ty * HDIM + j];
        float4 wu = reinterpret_cast<const float4*>(sWu)[j * 16 + q];
        float4 wv = reinterpret_cast<const float4*>(sWv)[j * 16 + q];
        au.x = fmaf(xj, wu.x, au.x); au.y = fmaf(xj, wu.y, au.y);
        au.z = fmaf(xj, wu.z, au.z); au.w = fmaf(xj, wu.w, au.w);
        av.x = fmaf(xj, wv.x, av.x); av.y = fmaf(xj, wv.y, av.y);
        av.z = fmaf(xj, wv.z, av.z); av.w = fmaf(xj, wv.w, av.w);
    }
    float4 bb = reinterpret_cast<const float4*>(b2)[q];
    au.x += bb.x; au.y += bb.y; au.z += bb.z; au.w += bb.w;
    reinterpret_cast<float4*>(g_A2)[i * 16 + q] = au;
    reinterpret_cast<float4*>(g_B2)[i * 16 + q] = av;
}

// ---------------------------------------------------------------------------
// K6: h2 = relu(A2 + max_k B2[idx]) folded directly into global max reduce
__global__ __launch_bounds__(256) void k_gmax2() {
    __shared__ int sg[HDIM];
    if (threadIdx.x < HDIM) sg[threadIdx.x] = 0;
    __syncthreads();
    int gt = blockIdx.x * 256 + threadIdx.x;
    int i = gt >> 4, q = gt & 15;
    const int* row = g_idx + i * KNN;
    float4 m = make_float4(FNINF, FNINF, FNINF, FNINF);
#pragma unroll
    for (int k = 0; k < KNN; ++k) {
        int j = __ldg(row + k);
        float4 v = reinterpret_cast<const float4*>(g_B2)[j * 16 + q];
        m.x = fmaxf(m.x, v.x); m.y = fmaxf(m.y, v.y);
        m.z = fmaxf(m.z, v.z); m.w = fmaxf(m.w, v.w);
    }
    float4 a = reinterpret_cast<const float4*>(g_A2)[i * 16 + q];
    float4 o;
    o.x = fmaxf(a.x + m.x, 0.0f); o.y = fmaxf(a.y + m.y, 0.0f);
    o.z = fmaxf(a.z + m.z, 0.0f); o.w = fmaxf(a.w + m.w, 0.0f);
    // relu outputs are >= 0, so int-compare == float-compare
    atomicMax(&sg[q * 4 + 0], __float_as_int(o.x));
    atomicMax(&sg[q * 4 + 1], __float_as_int(o.y));
    atomicMax(&sg[q * 4 + 2], __float_as_int(o.z));
    atomicMax(&sg[q * 4 + 3], __float_as_int(o.w));
    __syncthreads();
    if (threadIdx.x < HDIM) atomicMax(&g_gmax[threadIdx.x], sg[threadIdx.x]);
}

// ---------------------------------------------------------------------------
// K7: out = g @ Wc + bc   (1x64 @ 64x10)
__global__ void k_out(const float* __restrict__ Wc, const float* __restrict__ bc,
                      float* __restrict__ out) {
    int c = threadIdx.x;
    if (c >= CDIM) return;
    float acc = bc[c];
#pragma unroll
    for (int h = 0; h < HDIM; ++h)
        acc = fmaf(__int_as_float(g_gmax[h]), Wc[h * CDIM + c], acc);
    out[c] = acc;
}

// ---------------------------------------------------------------------------
extern "C" void kernel_launch(void* const* d_in, const int* in_sizes, int n_in,
                              void* d_out, int out_size) {
    const float* pos = (const float*)d_in[0];
    // d_in[1] = batch (all zeros, num_segments=1) -> unused
    const float* W1 = (const float*)d_in[2];
    const float* b1 = (const float*)d_in[3];
    const float* W2 = (const float*)d_in[4];
    const float* b2 = (const float*)d_in[5];
    const float* Wc = (const float*)d_in[6];
    const float* bc = (const float*)d_in[7];
    float* out = (float*)d_out;

    k_prep<<<NPTS / 256, 256>>>(pos);
    dim3 gk(NPTS / KBLK, NPART);
    k_knn<<<gk, KBLK>>>();
    k_merge<<<NPTS / 256, 256>>>();
    k_feat1<<<NPTS / 256, 256>>>(W1, b1);
    k_gmax1<<<NPTS * 16 / 256, 256>>>();
    k_feat2<<<NPTS / 16, 256>>>(W2, b2);
    k_gmax2<<<NPTS * 16 / 256, 256>>>();
    k_out<<<1, 32>>>(Wc, bc, out);
}

// round 2
// speedup vs baseline: 1.1337x; 1.1337x over previous
#include <cuda_runtime.h>

// Problem constants
#define NPTS 16384
#define KNN  16
#define HDIM 64
#define CDIM 10

// Spatial grid
#define GRID  32
#define NCELL (GRID * GRID * GRID)   // 32768
#define BMIN  (-5.0f)
#define CELLH 0.3125f                // 10/32
#define INVH  3.2f

#define FINF  __int_as_float(0x7f800000)
#define FNINF __int_as_float(0xff800000)

// ---- scratch (__device__ globals; no allocation allowed) ----
__device__ float4 g_pts[NPTS];       // original order: x,y,z,|p|^2
__device__ int    g_pcell[NPTS];     // cell id per original point
__device__ int    g_cnt[NCELL];      // per-cell counts
__device__ int    g_off[NCELL + 1];  // exclusive offsets
__device__ int    g_cur[NCELL];      // scatter cursors
__device__ float4 g_spts[NPTS];      // cell-sorted points
__device__ int    g_idx[NPTS * KNN]; // knn, in sorted-slot space
__device__ float  g_A1[NPTS * HDIM];
__device__ float  g_B1[NPTS * HDIM];
__device__ float  g_h1[NPTS * HDIM];
__device__ float  g_A2[NPTS * HDIM];
__device__ float  g_B2[NPTS * HDIM];
__device__ int    g_gmax[HDIM];      // global max (float-as-int, relu>=0)

__device__ __forceinline__ int cell_of(float v) {
    int c = (int)floorf((v - BMIN) * INVH);
    return min(max(c, 0), GRID - 1);
}

// ---------------------------------------------------------------------------
// K0: zero counters
__global__ void k_zero() {
    int i = blockIdx.x * blockDim.x + threadIdx.x;
    if (i < NCELL) g_cnt[i] = 0;
    if (i < HDIM)  g_gmax[i] = 0;
}

// K1: pack points, assign cells, histogram
__global__ void k_prep(const float* __restrict__ pos) {
    int i = blockIdx.x * blockDim.x + threadIdx.x;
    if (i >= NPTS) return;
    float x = pos[i * 3 + 0];
    float y = pos[i * 3 + 1];
    float z = pos[i * 3 + 2];
    g_pts[i] = make_float4(x, y, z, fmaf(z, z, fmaf(y, y, x * x)));
    int c = (cell_of(z) * GRID + cell_of(y)) * GRID + cell_of(x);
    g_pcell[i] = c;
    atomicAdd(&g_cnt[c], 1);
}

// K2: single-block exclusive scan over 32768 cells (1024 thr x 32 cells)
__global__ __launch_bounds__(1024) void k_scan() {
    __shared__ int s[1024];
    int t = threadIdx.x;
    int base = t * 32;
    int loc[32];
    int sum = 0;
#pragma unroll
    for (int k = 0; k < 32; ++k) { loc[k] = g_cnt[base + k]; sum += loc[k]; }
    s[t] = sum;
    __syncthreads();
    // Hillis-Steele inclusive scan
    for (int off = 1; off < 1024; off <<= 1) {
        int v = (t >= off) ? s[t - off] : 0;
        __syncthreads();
        s[t] += v;
        __syncthreads();
    }
    int run = s[t] - sum;  // exclusive base for this thread
#pragma unroll
    for (int k = 0; k < 32; ++k) {
        g_off[base + k] = run;
        g_cur[base + k] = run;
        run += loc[k];
    }
    if (t == 1023) g_off[NCELL] = NPTS;
}

// K3: scatter into sorted order
__global__ void k_scatter() {
    int i = blockIdx.x * blockDim.x + threadIdx.x;
    if (i >= NPTS) return;
    int c = g_pcell[i];
    int slot = atomicAdd(&g_cur[c], 1);
    g_spts[slot] = g_pts[i];
}

// ---------------------------------------------------------------------------
// K4: exact kNN via expanding-ring grid search. One thread per sorted slot;
// adjacent slots are spatially adjacent -> coherent warps.
__global__ __launch_bounds__(64) void k_knng() {
    int slot = blockIdx.x * 64 + threadIdx.x;
    float4 p = g_spts[slot];
    float ax = -2.0f * p.x, ay = -2.0f * p.y, az = -2.0f * p.z;
    int cx = cell_of(p.x), cy = cell_of(p.y), cz = cell_of(p.z);

    float dist[KNN];
    int   idxr[KNN];
#pragma unroll
    for (int s = 0; s < KNN; ++s) { dist[s] = FINF; idxr[s] = 0; }

    for (int m = 0; m < GRID; ++m) {
        int zlo = max(cz - m, 0), zhi = min(cz + m, GRID - 1);
        int ylo = max(cy - m, 0), yhi = min(cy + m, GRID - 1);
        int xlo = max(cx - m, 0), xhi = min(cx + m, GRID - 1);
        for (int z = zlo; z <= zhi; ++z) {
            int adz = abs(z - cz);
            for (int y = ylo; y <= yhi; ++y) {
                int ady = max(adz, abs(y - cy));
                bool full = (ady == m);
                int xstep = full ? 1 : 2 * m;
                int x0 = full ? xlo : (cx - m);
                for (int x = x0; x <= xhi; x += (xstep > 0 ? xstep : 1)) {
                    if (x < xlo) continue;              // clipped edge column
                    int c = (z * GRID + y) * GRID + x;
                    int s0 = g_off[c], s1 = g_off[c + 1];
                    for (int j = s0; j < s1; ++j) {
                        float4 cd = g_spts[j];
                        float d = fmaf(ax, cd.x,
                                  fmaf(ay, cd.y,
                                  fmaf(az, cd.z, cd.w + p.w)));
                        if (d < dist[KNN - 1]) {
                            int jj = j;
#pragma unroll
                            for (int s = 0; s < KNN; ++s) {
                                bool cnd = d < dist[s];
                                float td = dist[s]; int ti = idxr[s];
                                dist[s] = cnd ? d : td;
                                idxr[s] = cnd ? jj : ti;
                                d  = cnd ? td : d;
                                jj = cnd ? ti : jj;
                            }
                        }
                    }
                    if (!full && (2 * m) == 0) break;   // m==0: single cell
                }
            }
        }
        // all unscanned cells are at Chebyshev >= m+1 -> true dist >= m*h
        float bnd = (float)m * CELLH;
        if (dist[KNN - 1] <= bnd * bnd) break;
    }
    int off = slot * KNN;
#pragma unroll
    for (int s = 0; s < KNN; ++s) g_idx[off + s] = idxr[s];
}

// ---------------------------------------------------------------------------
// K5: layer-1 projections (blocked, coalesced). A1 = x@(Wa-Wb)+b1, B1 = x@Wb
__global__ __launch_bounds__(256) void k_feat1(const float* __restrict__ W1,
                                               const float* __restrict__ b1) {
    __shared__ float sW[6 * HDIM];
    __shared__ float sb[HDIM];
    int tid = threadIdx.x;
    for (int e = tid; e < 6 * HDIM; e += 256) sW[e] = W1[e];
    if (tid < HDIM) sb[tid] = b1[tid];
    __syncthreads();
    int ty = tid >> 4, q = tid & 15;
    int i = blockIdx.x * 16 + ty;
    float4 p = g_spts[i];
    float4 u, v;
    float* up = &u.x; float* vp = &v.x;
#pragma unroll
    for (int e = 0; e < 4; ++e) {
        int h = q * 4 + e;
        float wa0 = sW[0 * HDIM + h], wa1 = sW[1 * HDIM + h], wa2 = sW[2 * HDIM + h];
        float wb0 = sW[3 * HDIM + h], wb1 = sW[4 * HDIM + h], wb2 = sW[5 * HDIM + h];
        vp[e] = fmaf(p.x, wb0, fmaf(p.y, wb1, p.z * wb2));
        up[e] = fmaf(p.x, wa0 - wb0, fmaf(p.y, wa1 - wb1, p.z * (wa2 - wb2))) + sb[h];
    }
    reinterpret_cast<float4*>(g_A1)[i * 16 + q] = u;
    reinterpret_cast<float4*>(g_B1)[i * 16 + q] = v;
}

// ---------------------------------------------------------------------------
// K6: h1 = relu(A1 + max_k B1[idx])
__global__ __launch_bounds__(256) void k_gmax1() {
    int gt = blockIdx.x * 256 + threadIdx.x;
    int i = gt >> 4, q = gt & 15;
    const int* row = g_idx + i * KNN;
    float4 m = make_float4(FNINF, FNINF, FNINF, FNINF);
#pragma unroll
    for (int k = 0; k < KNN; ++k) {
        int j = __ldg(row + k);
        float4 v = reinterpret_cast<const float4*>(g_B1)[j * 16 + q];
        m.x = fmaxf(m.x, v.x); m.y = fmaxf(m.y, v.y);
        m.z = fmaxf(m.z, v.z); m.w = fmaxf(m.w, v.w);
    }
    float4 a = reinterpret_cast<const float4*>(g_A1)[i * 16 + q];
    float4 o;
    o.x = fmaxf(a.x + m.x, 0.0f); o.y = fmaxf(a.y + m.y, 0.0f);
    o.z = fmaxf(a.z + m.z, 0.0f); o.w = fmaxf(a.w + m.w, 0.0f);
    reinterpret_cast<float4*>(g_h1)[i * 16 + q] = o;
}

// ---------------------------------------------------------------------------
// K7: layer-2 projections. A2 = h1@(W2a-W2b)+b2, B2 = h1@W2b
__global__ __launch_bounds__(256) void k_feat2(const float* __restrict__ W2,
                                               const float* __restrict__ b2) {
    __shared__ float sWu[HDIM * HDIM];
    __shared__ float sWv[HDIM * HDIM];
    __shared__ float sX[16 * HDIM];
    int tid = threadIdx.x;
    for (int e = tid; e < HDIM * HDIM; e += 256) {
        int j = e >> 6, h = e & 63;
        float wb = W2[(j + HDIM) * HDIM + h];
        sWv[e] = wb;
        sWu[e] = W2[j * HDIM + h] - wb;
    }
    int ty = tid >> 4, q = tid & 15;
    int i = blockIdx.x * 16 + ty;
    reinterpret_cast<float4*>(sX)[ty * 16 + q] =
        reinterpret_cast<const float4*>(g_h1)[i * 16 + q];
    __syncthreads();

    float4 au = make_float4(0.f, 0.f, 0.f, 0.f);
    float4 av = make_float4(0.f, 0.f, 0.f, 0.f);
#pragma unroll 8
    for (int j = 0; j < HDIM; ++j) {
        float xj = sX[ty * HDIM + j];
        float4 wu = reinterpret_cast<const float4*>(sWu)[j * 16 + q];
        float4 wv = reinterpret_cast<const float4*>(sWv)[j * 16 + q];
        au.x = fmaf(xj, wu.x, au.x); au.y = fmaf(xj, wu.y, au.y);
        au.z = fmaf(xj, wu.z, au.z); au.w = fmaf(xj, wu.w, au.w);
        av.x = fmaf(xj, wv.x, av.x); av.y = fmaf(xj, wv.y, av.y);
        av.z = fmaf(xj, wv.z, av.z); av.w = fmaf(xj, wv.w, av.w);
    }
    float4 bb = reinterpret_cast<const float4*>(b2)[q];
    au.x += bb.x; au.y += bb.y; au.z += bb.z; au.w += bb.w;
    reinterpret_cast<float4*>(g_A2)[i * 16 + q] = au;
    reinterpret_cast<float4*>(g_B2)[i * 16 + q] = av;
}

// ---------------------------------------------------------------------------
// K8: h2 = relu(A2 + max_k B2[idx]) folded into global max reduce
__global__ __launch_bounds__(256) void k_gmax2() {
    __shared__ int sg[HDIM];
    if (threadIdx.x < HDIM) sg[threadIdx.x] = 0;
    __syncthreads();
    int gt = blockIdx.x * 256 + threadIdx.x;
    int i = gt >> 4, q = gt & 15;
    const int* row = g_idx + i * KNN;
    float4 m = make_float4(FNINF, FNINF, FNINF, FNINF);
#pragma unroll
    for (int k = 0; k < KNN; ++k) {
        int j = __ldg(row + k);
        float4 v = reinterpret_cast<const float4*>(g_B2)[j * 16 + q];
        m.x = fmaxf(m.x, v.x); m.y = fmaxf(m.y, v.y);
        m.z = fmaxf(m.z, v.z); m.w = fmaxf(m.w, v.w);
    }
    float4 a = reinterpret_cast<const float4*>(g_A2)[i * 16 + q];
    float4 o;
    o.x = fmaxf(a.x + m.x, 0.0f); o.y = fmaxf(a.y + m.y, 0.0f);
    o.z = fmaxf(a.z + m.z, 0.0f); o.w = fmaxf(a.w + m.w, 0.0f);
    atomicMax(&sg[q * 4 + 0], __float_as_int(o.x));
    atomicMax(&sg[q * 4 + 1], __float_as_int(o.y));
    atomicMax(&sg[q * 4 + 2], __float_as_int(o.z));
    atomicMax(&sg[q * 4 + 3], __float_as_int(o.w));
    __syncthreads();
    if (threadIdx.x < HDIM) atomicMax(&g_gmax[threadIdx.x], sg[threadIdx.x]);
}

// ---------------------------------------------------------------------------
// K9: out = g @ Wc + bc
__global__ void k_out(const float* __restrict__ Wc, const float* __restrict__ bc,
                      float* __restrict__ out) {
    int c = threadIdx.x;
    if (c >= CDIM) return;
    float acc = bc[c];
#pragma unroll
    for (int h = 0; h < HDIM; ++h)
        acc = fmaf(__int_as_float(g_gmax[h]), Wc[h * CDIM + c], acc);
    out[c] = acc;
}

// ---------------------------------------------------------------------------
extern "C" void kernel_launch(void* const* d_in, const int* in_sizes, int n_in,
                              void* d_out, int out_size) {
    const float* pos = (const float*)d_in[0];
    // d_in[1] = batch (all zeros, num_segments=1) -> unused
    const float* W1 = (const float*)d_in[2];
    const float* b1 = (const float*)d_in[3];
    const float* W2 = (const float*)d_in[4];
    const float* b2 = (const float*)d_in[5];
    const float* Wc = (const float*)d_in[6];
    const float* bc = (const float*)d_in[7];
    float* out = (float*)d_out;

    k_zero<<<NCELL / 256, 256>>>();
    k_prep<<<NPTS / 256, 256>>>(pos);
    k_scan<<<1, 1024>>>();
    k_scatter<<<NPTS / 256, 256>>>();
    k_knng<<<NPTS / 64, 64>>>();
    k_feat1<<<NPTS / 16, 256>>>(W1, b1);
    k_gmax1<<<NPTS * 16 / 256, 256>>>();
    k_feat2<<<NPTS / 16, 256>>>(W2, b2);
    k_gmax2<<<NPTS * 16 / 256, 256>>>();
    k_out<<<1, 32>>>(Wc, bc, out);
}